// round 5
// baseline (speedup 1.0000x reference)
#include <cuda_runtime.h>

// Problem constants
#define N   6144
#define T   512            // threads per attention block
#define JPT (N / T)        // 12 j-indices owned per thread
#define GRID 148           // one persistent block per SM (1 wave)

// Projection indices in d_proj
// 0: g1 (= lin(q1)+lin(q2))   1: g2 (= lin(q3)+lin(q4))
// 2: k1   3: k2   4: v1   5: v2
__device__ float d_proj[6][3][N];   // SoA: [proj][component][token]
__device__ float d_y2[N * 3];       // (a2 @ v2) rows, from matrix-2 kernel

// ---------------------------------------------------------------------------
// Kernel 1: all 6 projection rows per token (each is x[3] @ W^T + b).
// group1/group2 weights are combined: (xW1^T+b1)+(xW2^T+b2) = x(W1+W2)^T+(b1+b2)
// ---------------------------------------------------------------------------
__global__ void proj_kernel(
    const float* __restrict__ x,
    const float* __restrict__ wq1, const float* __restrict__ bq1,
    const float* __restrict__ wq2, const float* __restrict__ bq2,
    const float* __restrict__ wq3, const float* __restrict__ bq3,
    const float* __restrict__ wq4, const float* __restrict__ bq4,
    const float* __restrict__ wk1, const float* __restrict__ bk1,
    const float* __restrict__ wk2, const float* __restrict__ bk2,
    const float* __restrict__ wv1, const float* __restrict__ bv1,
    const float* __restrict__ wv2, const float* __restrict__ bv2)
{
    int i = blockIdx.x * blockDim.x + threadIdx.x;
    if (i >= N) return;
    float x0 = x[3 * i + 0], x1 = x[3 * i + 1], x2 = x[3 * i + 2];

    // g1 = lin(q1)+lin(q2) with combined weights
    #pragma unroll
    for (int c = 0; c < 3; c++) {
        float v = (bq1[c] + bq2[c])
                + (wq1[c * 3 + 0] + wq2[c * 3 + 0]) * x0
                + (wq1[c * 3 + 1] + wq2[c * 3 + 1]) * x1
                + (wq1[c * 3 + 2] + wq2[c * 3 + 2]) * x2;
        d_proj[0][c][i] = v;
    }
    // g2 = lin(q3)+lin(q4)
    #pragma unroll
    for (int c = 0; c < 3; c++) {
        float v = (bq3[c] + bq4[c])
                + (wq3[c * 3 + 0] + wq4[c * 3 + 0]) * x0
                + (wq3[c * 3 + 1] + wq4[c * 3 + 1]) * x1
                + (wq3[c * 3 + 2] + wq4[c * 3 + 2]) * x2;
        d_proj[1][c][i] = v;
    }
    // k1, k2, v1, v2
    const float* WS[4] = { wk1, wk2, wv1, wv2 };
    const float* BS[4] = { bk1, bk2, bv1, bv2 };
    #pragma unroll
    for (int p = 0; p < 4; p++) {
        const float* W = WS[p];
        const float* B = BS[p];
        #pragma unroll
        for (int c = 0; c < 3; c++) {
            float v = B[c] + W[c * 3 + 0] * x0 + W[c * 3 + 1] * x1 + W[c * 3 + 2] * x2;
            d_proj[2 + p][c][i] = v;
        }
    }
}

// ---------------------------------------------------------------------------
// Kernel 2/3: fused attention.
//   Each block owns a balanced contiguous range of rows i.
//   Each thread permanently holds k[PK], v[PV] for its 12 contiguous j's in
//   REGISTERS (zero smem/L2 traffic in the mainloop).
//   Per row: logits -> exp (single MUFU.EX2, g pre-scaled by log2e) -> row sum
//   and (e . v) accumulated, block-reduced, then (WRITE path only) the
//   register-resident e values are normalized and written as float4 STG.128.
//   No softmax-max pass: |logit| is bounded ~10 << fp32 exp range; matches
//   reference to ~1e-6 rel.
//   WRITE=false  : matrix 2 -> writes only d_y2[i] = (a2 @ v2)_i
//   WRITE=true   : matrix 1 -> writes a1 row and fuses the final Linear:
//                  b_i = Wb (a1@v1 + y2)_i + bb
// ---------------------------------------------------------------------------
template <int PG, int PK, int PV, bool WRITE>
__global__ void __launch_bounds__(T, 1) attn_kernel(
    float* __restrict__ a_out,        // [N,N] (WRITE only)
    float* __restrict__ b_out,        // [N,3] (WRITE only)
    const float* __restrict__ wb,     // [3,3] (WRITE only)
    const float* __restrict__ bb)     // [3]   (WRITE only)
{
    const int t  = threadIdx.x;
    const int j0 = t * JPT;

    // Load this thread's K/V slice into registers (float4 vectorized).
    float kx[JPT], ky[JPT], kz[JPT], vx[JPT], vy[JPT], vz[JPT];
    #pragma unroll
    for (int q = 0; q < JPT / 4; q++) {
        float4 f;
        f = *(const float4*)&d_proj[PK][0][j0 + 4 * q];
        kx[4*q] = f.x; kx[4*q+1] = f.y; kx[4*q+2] = f.z; kx[4*q+3] = f.w;
        f = *(const float4*)&d_proj[PK][1][j0 + 4 * q];
        ky[4*q] = f.x; ky[4*q+1] = f.y; ky[4*q+2] = f.z; ky[4*q+3] = f.w;
        f = *(const float4*)&d_proj[PK][2][j0 + 4 * q];
        kz[4*q] = f.x; kz[4*q+1] = f.y; kz[4*q+2] = f.z; kz[4*q+3] = f.w;
        f = *(const float4*)&d_proj[PV][0][j0 + 4 * q];
        vx[4*q] = f.x; vx[4*q+1] = f.y; vx[4*q+2] = f.z; vx[4*q+3] = f.w;
        f = *(const float4*)&d_proj[PV][1][j0 + 4 * q];
        vy[4*q] = f.x; vy[4*q+1] = f.y; vy[4*q+2] = f.z; vy[4*q+3] = f.w;
        f = *(const float4*)&d_proj[PV][2][j0 + 4 * q];
        vz[4*q] = f.x; vz[4*q+1] = f.y; vz[4*q+2] = f.z; vz[4*q+3] = f.w;
    }

    __shared__ float red[(T / 32) * 4];
    __shared__ float tot[4];
    __shared__ float s_inv;

    // Balanced contiguous row split across GRID blocks.
    const int r0 = (int)(((long long)N * blockIdx.x) / gridDim.x);
    const int r1 = (int)(((long long)N * (blockIdx.x + 1)) / gridDim.x);

    const float LOG2E = 1.4426950408889634f;

    for (int i = r0; i < r1; i++) {
        // Broadcast g_i, pre-scaled by log2(e) so exp(l) = exp2f(dot).
        float gx = d_proj[PG][0][i] * LOG2E;
        float gy = d_proj[PG][1][i] * LOG2E;
        float gz = d_proj[PG][2][i] * LOG2E;

        float e[JPT];
        float sum = 0.f, ax = 0.f, ay = 0.f, az = 0.f;
        #pragma unroll
        for (int s = 0; s < JPT; s++) {
            float l  = fmaf(gx, kx[s], fmaf(gy, ky[s], gz * kz[s]));
            float ev = exp2f(l);          // MUFU.EX2
            e[s] = ev;
            sum += ev;
            ax = fmaf(ev, vx[s], ax);
            ay = fmaf(ev, vy[s], ay);
            az = fmaf(ev, vz[s], az);
        }

        // Warp reduce 4 values.
        #pragma unroll
        for (int o = 16; o > 0; o >>= 1) {
            sum += __shfl_xor_sync(0xffffffffu, sum, o);
            ax  += __shfl_xor_sync(0xffffffffu, ax,  o);
            ay  += __shfl_xor_sync(0xffffffffu, ay,  o);
            az  += __shfl_xor_sync(0xffffffffu, az,  o);
        }
        if ((t & 31) == 0) {
            int w = t >> 5;
            red[w * 4 + 0] = sum;
            red[w * 4 + 1] = ax;
            red[w * 4 + 2] = ay;
            red[w * 4 + 3] = az;
        }
        __syncthreads();
        if (t < 4) {
            float a = 0.f;
            #pragma unroll
            for (int w = 0; w < T / 32; w++) a += red[w * 4 + t];
            tot[t] = a;
            if (t == 0) s_inv = 1.0f / a;   // a == row sum for t==0
        }
        __syncthreads();

        const float inv = s_inv;

        if (WRITE) {
            // Normalized a1 row write, 3x STG.128 per thread.
            float4* dst = (float4*)(a_out + (size_t)i * N + j0);
            #pragma unroll
            for (int q = 0; q < JPT / 4; q++) {
                float4 o;
                o.x = e[4*q+0] * inv;
                o.y = e[4*q+1] * inv;
                o.z = e[4*q+2] * inv;
                o.w = e[4*q+3] * inv;
                dst[q] = o;
            }
            if (t == 0) {
                // y = (a1@v1)_i + (a2@v2)_i ; b_i = Wb y + bb
                float y0 = tot[1] * inv + d_y2[i * 3 + 0];
                float y1 = tot[2] * inv + d_y2[i * 3 + 1];
                float y2 = tot[3] * inv + d_y2[i * 3 + 2];
                #pragma unroll
                for (int c = 0; c < 3; c++)
                    b_out[i * 3 + c] = bb[c] + wb[c * 3 + 0] * y0
                                             + wb[c * 3 + 1] * y1
                                             + wb[c * 3 + 2] * y2;
            }
        } else {
            if (t == 0) {
                d_y2[i * 3 + 0] = tot[1] * inv;
                d_y2[i * 3 + 1] = tot[2] * inv;
                d_y2[i * 3 + 2] = tot[3] * inv;
            }
        }
    }
}

// ---------------------------------------------------------------------------
// Launch: proj -> matrix2 (y2) -> matrix1 (a1 + fused final Linear -> b)
// Output layout: a1 [N*N] followed by b [N*3].
// ---------------------------------------------------------------------------
extern "C" void kernel_launch(void* const* d_in, const int* in_sizes, int n_in,
                              void* d_out, int out_size)
{
    const float* x   = (const float*)d_in[0];
    const float* wq1 = (const float*)d_in[1];
    const float* bq1 = (const float*)d_in[2];
    const float* wq2 = (const float*)d_in[3];
    const float* bq2 = (const float*)d_in[4];
    const float* wq3 = (const float*)d_in[5];
    const float* bq3 = (const float*)d_in[6];
    const float* wq4 = (const float*)d_in[7];
    const float* bq4 = (const float*)d_in[8];
    const float* wk1 = (const float*)d_in[9];
    const float* bk1 = (const float*)d_in[10];
    const float* wk2 = (const float*)d_in[11];
    const float* bk2 = (const float*)d_in[12];
    const float* wv1 = (const float*)d_in[13];
    const float* bv1 = (const float*)d_in[14];
    const float* wv2 = (const float*)d_in[15];
    const float* bv2 = (const float*)d_in[16];
    const float* wb  = (const float*)d_in[17];
    const float* bb  = (const float*)d_in[18];

    float* out = (float*)d_out;
    float* a1  = out;                       // [N, N]
    float* b   = out + (size_t)N * N;       // [N, 3]

    proj_kernel<<<(N + 255) / 256, 256>>>(
        x, wq1, bq1, wq2, bq2, wq3, bq3, wq4, bq4,
        wk1, bk1, wk2, bk2, wv1, bv1, wv2, bv2);

    // Matrix 2: g2/k2/v2, produce d_y2 only.
    attn_kernel<1, 3, 5, false><<<GRID, T>>>(nullptr, nullptr, nullptr, nullptr);

    // Matrix 1: g1/k1/v1, write a1 and fused b.
    attn_kernel<0, 2, 4, true><<<GRID, T>>>(a1, b, wb, bb);
}

// round 6
// speedup vs baseline: 1.1059x; 1.1059x over previous
#include <cuda_runtime.h>

// Problem constants
#define N    6144
#define T    512            // threads per block
#define JPT  (N / T)        // 12 j-indices owned per thread
#define GRID 148            // one persistent block per SM (1 wave)
#define MAXR 48             // max rows per block (6144/148 -> 41 or 42)

// MUFU.EX2 (approximate exp2) — forced via PTX so we never get the slow
// accurate-polynomial exp2f.
__device__ __forceinline__ float ex2(float v) {
    float r;
    asm("ex2.approx.f32 %0, %1;" : "=f"(r) : "f"(v));
    return r;
}

struct Smem {
    float sg[MAXR][3];    // current phase's g rows, pre-scaled by log2(e)
    float y2[MAXR][3];    // (a2 @ v2) rows for this block's row range
    float red[16][9];     // per-warp partials (padded to 9 to dodge bank conflicts)
    float tot[8];         // block totals: [sum,ax,ay,az] x 2 rows
    float sinv[2];        // 1/rowsum for the two rows in flight
};

// ---------------------------------------------------------------------------
// Single fused kernel. Per block: contiguous balanced row range [r0, r1).
//  Phase A (g2/k2/v2): compute y2[i] = (softmax(g2 k2^T) @ v2)_i into SMEM.
//  Phase B (g1/k1/v1): write normalized a1 rows (register-resident e values,
//    single MUFU.EX2 per element, no max pass — |logit| ~ 10 << fp32 range)
//    and the fused final Linear b_i = Wb((a1@v1)_i + y2_i) + bb.
//  K/V for each phase live entirely in REGISTERS (12 j's per thread), computed
//  directly from x — no projection kernel, no global scratch at all.
//  Two rows are processed per iteration to amortize the block reduction, and
//  stage-2 of the reduction runs as a 4-step shuffle across 128 threads.
// ---------------------------------------------------------------------------
__global__ void __launch_bounds__(T, 1) fused_gqa_kernel(
    const float* __restrict__ x,
    const float* __restrict__ wq1, const float* __restrict__ bq1,
    const float* __restrict__ wq2, const float* __restrict__ bq2,
    const float* __restrict__ wq3, const float* __restrict__ bq3,
    const float* __restrict__ wq4, const float* __restrict__ bq4,
    const float* __restrict__ wk1, const float* __restrict__ bk1,
    const float* __restrict__ wk2, const float* __restrict__ bk2,
    const float* __restrict__ wv1, const float* __restrict__ bv1,
    const float* __restrict__ wv2, const float* __restrict__ bv2,
    const float* __restrict__ wb,  const float* __restrict__ bb,
    float* __restrict__ a_out,     // [N, N]
    float* __restrict__ b_out)     // [N, 3]
{
    __shared__ Smem sm;

    const int t  = threadIdx.x;
    const int j0 = t * JPT;
    const int r0 = (int)(((long long)N * blockIdx.x) / GRID);
    const int r1 = (int)(((long long)N * (blockIdx.x + 1)) / GRID);
    const int nr = r1 - r0;
    const float LOG2E = 1.4426950408889634f;

    float kx[JPT], ky[JPT], kz[JPT], vx[JPT], vy[JPT], vz[JPT];

    // =======================================================================
    // Phase A: matrix 2 (g2 = lin(q3)+lin(q4), k2, v2) -> y2 rows in SMEM
    // =======================================================================
    {
        // K2/V2 for this thread's j slice, straight from x (float4 loads).
        float xs[3 * JPT];
        const float4* xp = (const float4*)(x + 3 * j0);
        #pragma unroll
        for (int q = 0; q < (3 * JPT) / 4; q++) {
            float4 f = xp[q];
            xs[4*q] = f.x; xs[4*q+1] = f.y; xs[4*q+2] = f.z; xs[4*q+3] = f.w;
        }
        #pragma unroll
        for (int s = 0; s < JPT; s++) {
            float X0 = xs[3*s], X1 = xs[3*s+1], X2 = xs[3*s+2];
            kx[s] = bk2[0] + wk2[0]*X0 + wk2[1]*X1 + wk2[2]*X2;
            ky[s] = bk2[1] + wk2[3]*X0 + wk2[4]*X1 + wk2[5]*X2;
            kz[s] = bk2[2] + wk2[6]*X0 + wk2[7]*X1 + wk2[8]*X2;
            vx[s] = bv2[0] + wv2[0]*X0 + wv2[1]*X1 + wv2[2]*X2;
            vy[s] = bv2[1] + wv2[3]*X0 + wv2[4]*X1 + wv2[5]*X2;
            vz[s] = bv2[2] + wv2[6]*X0 + wv2[7]*X1 + wv2[8]*X2;
        }
        // g2 rows for the block's range (combined q3+q4 weights), *log2e.
        if (t < nr) {
            int i = r0 + t;
            float X0 = x[3*i], X1 = x[3*i+1], X2 = x[3*i+2];
            #pragma unroll
            for (int c = 0; c < 3; c++) {
                float v = (bq3[c] + bq4[c])
                        + (wq3[c*3+0] + wq4[c*3+0]) * X0
                        + (wq3[c*3+1] + wq4[c*3+1]) * X1
                        + (wq3[c*3+2] + wq4[c*3+2]) * X2;
                sm.sg[t][c] = v * LOG2E;
            }
        }
    }
    __syncthreads();

    for (int ii = 0; ii < nr; ii += 2) {
        const int  l2v = (ii + 1 < nr);
        const int  lr2 = l2v ? ii + 1 : ii;

        float g1x = sm.sg[ii][0],  g1y = sm.sg[ii][1],  g1z = sm.sg[ii][2];
        float g2x = sm.sg[lr2][0], g2y = sm.sg[lr2][1], g2z = sm.sg[lr2][2];

        float r[8] = {0,0,0,0,0,0,0,0};   // [sum,ax,ay,az] x 2 rows
        #pragma unroll
        for (int s = 0; s < JPT; s++) {
            float l1 = fmaf(g1x, kx[s], fmaf(g1y, ky[s], g1z * kz[s]));
            float l2 = fmaf(g2x, kx[s], fmaf(g2y, ky[s], g2z * kz[s]));
            float e1 = ex2(l1);
            float e2 = ex2(l2);
            r[0] += e1;                       r[4] += e2;
            r[1] = fmaf(e1, vx[s], r[1]);     r[5] = fmaf(e2, vx[s], r[5]);
            r[2] = fmaf(e1, vy[s], r[2]);     r[6] = fmaf(e2, vy[s], r[6]);
            r[3] = fmaf(e1, vz[s], r[3]);     r[7] = fmaf(e2, vz[s], r[7]);
        }
        #pragma unroll
        for (int o = 16; o > 0; o >>= 1) {
            #pragma unroll
            for (int q = 0; q < 8; q++) r[q] += __shfl_xor_sync(0xffffffffu, r[q], o);
        }
        if ((t & 31) == 0) {
            int w = t >> 5;
            #pragma unroll
            for (int q = 0; q < 8; q++) sm.red[w][q] = r[q];
        }
        __syncthreads();
        if (t < 128) {                      // stage 2: 16 partials per quantity
            int q = t >> 4, w = t & 15;
            float v = sm.red[w][q];
            #pragma unroll
            for (int o = 8; o > 0; o >>= 1) v += __shfl_xor_sync(0xffffffffu, v, o);
            if (w == 0) {
                sm.tot[q] = v;
                if (q == 0) sm.sinv[0] = 1.0f / v;
                if (q == 4) sm.sinv[1] = 1.0f / v;
            }
        }
        __syncthreads();
        if (t == 0) {
            float inv = sm.sinv[0];
            sm.y2[ii][0] = sm.tot[1] * inv;
            sm.y2[ii][1] = sm.tot[2] * inv;
            sm.y2[ii][2] = sm.tot[3] * inv;
        }
        if (t == 32 && l2v) {
            float inv = sm.sinv[1];
            sm.y2[ii+1][0] = sm.tot[5] * inv;
            sm.y2[ii+1][1] = sm.tot[6] * inv;
            sm.y2[ii+1][2] = sm.tot[7] * inv;
        }
    }
    __syncthreads();

    // =======================================================================
    // Phase B: matrix 1 (g1 = lin(q1)+lin(q2), k1, v1) -> a1 rows + fused b
    // =======================================================================
    {
        float xs[3 * JPT];
        const float4* xp = (const float4*)(x + 3 * j0);
        #pragma unroll
        for (int q = 0; q < (3 * JPT) / 4; q++) {
            float4 f = xp[q];
            xs[4*q] = f.x; xs[4*q+1] = f.y; xs[4*q+2] = f.z; xs[4*q+3] = f.w;
        }
        #pragma unroll
        for (int s = 0; s < JPT; s++) {
            float X0 = xs[3*s], X1 = xs[3*s+1], X2 = xs[3*s+2];
            kx[s] = bk1[0] + wk1[0]*X0 + wk1[1]*X1 + wk1[2]*X2;
            ky[s] = bk1[1] + wk1[3]*X0 + wk1[4]*X1 + wk1[5]*X2;
            kz[s] = bk1[2] + wk1[6]*X0 + wk1[7]*X1 + wk1[8]*X2;
            vx[s] = bv1[0] + wv1[0]*X0 + wv1[1]*X1 + wv1[2]*X2;
            vy[s] = bv1[1] + wv1[3]*X0 + wv1[4]*X1 + wv1[5]*X2;
            vz[s] = bv1[2] + wv1[6]*X0 + wv1[7]*X1 + wv1[8]*X2;
        }
        if (t < nr) {
            int i = r0 + t;
            float X0 = x[3*i], X1 = x[3*i+1], X2 = x[3*i+2];
            #pragma unroll
            for (int c = 0; c < 3; c++) {
                float v = (bq1[c] + bq2[c])
                        + (wq1[c*3+0] + wq2[c*3+0]) * X0
                        + (wq1[c*3+1] + wq2[c*3+1]) * X1
                        + (wq1[c*3+2] + wq2[c*3+2]) * X2;
                sm.sg[t][c] = v * LOG2E;
            }
        }
    }
    __syncthreads();

    for (int ii = 0; ii < nr; ii += 2) {
        const int  l2v = (ii + 1 < nr);
        const int  lr2 = l2v ? ii + 1 : ii;

        float g1x = sm.sg[ii][0],  g1y = sm.sg[ii][1],  g1z = sm.sg[ii][2];
        float g2x = sm.sg[lr2][0], g2y = sm.sg[lr2][1], g2z = sm.sg[lr2][2];

        float e1a[JPT], e2a[JPT];
        float r[8] = {0,0,0,0,0,0,0,0};
        #pragma unroll
        for (int s = 0; s < JPT; s++) {
            float l1 = fmaf(g1x, kx[s], fmaf(g1y, ky[s], g1z * kz[s]));
            float l2 = fmaf(g2x, kx[s], fmaf(g2y, ky[s], g2z * kz[s]));
            float e1 = ex2(l1);
            float e2 = ex2(l2);
            e1a[s] = e1;                      e2a[s] = e2;
            r[0] += e1;                       r[4] += e2;
            r[1] = fmaf(e1, vx[s], r[1]);     r[5] = fmaf(e2, vx[s], r[5]);
            r[2] = fmaf(e1, vy[s], r[2]);     r[6] = fmaf(e2, vy[s], r[6]);
            r[3] = fmaf(e1, vz[s], r[3]);     r[7] = fmaf(e2, vz[s], r[7]);
        }
        #pragma unroll
        for (int o = 16; o > 0; o >>= 1) {
            #pragma unroll
            for (int q = 0; q < 8; q++) r[q] += __shfl_xor_sync(0xffffffffu, r[q], o);
        }
        if ((t & 31) == 0) {
            int w = t >> 5;
            #pragma unroll
            for (int q = 0; q < 8; q++) sm.red[w][q] = r[q];
        }
        __syncthreads();
        if (t < 128) {
            int q = t >> 4, w = t & 15;
            float v = sm.red[w][q];
            #pragma unroll
            for (int o = 8; o > 0; o >>= 1) v += __shfl_xor_sync(0xffffffffu, v, o);
            if (w == 0) {
                sm.tot[q] = v;
                if (q == 0) sm.sinv[0] = 1.0f / v;
                if (q == 4) sm.sinv[1] = 1.0f / v;
            }
        }
        __syncthreads();

        const float inv0 = sm.sinv[0];
        const float inv1 = sm.sinv[1];

        // Normalized a1 rows: 3x STG.128 per thread per row.
        float4* dst1 = (float4*)(a_out + (size_t)(r0 + ii) * N + j0);
        #pragma unroll
        for (int q = 0; q < JPT / 4; q++) {
            float4 o;
            o.x = e1a[4*q+0] * inv0; o.y = e1a[4*q+1] * inv0;
            o.z = e1a[4*q+2] * inv0; o.w = e1a[4*q+3] * inv0;
            dst1[q] = o;
        }
        if (l2v) {
            float4* dst2 = (float4*)(a_out + (size_t)(r0 + ii + 1) * N + j0);
            #pragma unroll
            for (int q = 0; q < JPT / 4; q++) {
                float4 o;
                o.x = e2a[4*q+0] * inv1; o.y = e2a[4*q+1] * inv1;
                o.z = e2a[4*q+2] * inv1; o.w = e2a[4*q+3] * inv1;
                dst2[q] = o;
            }
        }
        // Fused final Linear: b_i = Wb((a1@v1)_i + y2_i) + bb
        if (t == 0) {
            int i = r0 + ii;
            float y0 = sm.tot[1] * inv0 + sm.y2[ii][0];
            float y1 = sm.tot[2] * inv0 + sm.y2[ii][1];
            float y2 = sm.tot[3] * inv0 + sm.y2[ii][2];
            #pragma unroll
            for (int c = 0; c < 3; c++)
                b_out[i*3+c] = bb[c] + wb[c*3+0]*y0 + wb[c*3+1]*y1 + wb[c*3+2]*y2;
        }
        if (t == 32 && l2v) {
            int i = r0 + ii + 1;
            float y0 = sm.tot[5] * inv1 + sm.y2[ii+1][0];
            float y1 = sm.tot[6] * inv1 + sm.y2[ii+1][1];
            float y2 = sm.tot[7] * inv1 + sm.y2[ii+1][2];
            #pragma unroll
            for (int c = 0; c < 3; c++)
                b_out[i*3+c] = bb[c] + wb[c*3+0]*y0 + wb[c*3+1]*y1 + wb[c*3+2]*y2;
        }
    }
}

// ---------------------------------------------------------------------------
// Single launch. Output layout: a1 [N*N] followed by b [N*3].
// ---------------------------------------------------------------------------
extern "C" void kernel_launch(void* const* d_in, const int* in_sizes, int n_in,
                              void* d_out, int out_size)
{
    const float* x   = (const float*)d_in[0];
    const float* wq1 = (const float*)d_in[1];
    const float* bq1 = (const float*)d_in[2];
    const float* wq2 = (const float*)d_in[3];
    const float* bq2 = (const float*)d_in[4];
    const float* wq3 = (const float*)d_in[5];
    const float* bq3 = (const float*)d_in[6];
    const float* wq4 = (const float*)d_in[7];
    const float* bq4 = (const float*)d_in[8];
    const float* wk1 = (const float*)d_in[9];
    const float* bk1 = (const float*)d_in[10];
    const float* wk2 = (const float*)d_in[11];
    const float* bk2 = (const float*)d_in[12];
    const float* wv1 = (const float*)d_in[13];
    const float* bv1 = (const float*)d_in[14];
    const float* wv2 = (const float*)d_in[15];
    const float* bv2 = (const float*)d_in[16];
    const float* wb  = (const float*)d_in[17];
    const float* bb  = (const float*)d_in[18];

    float* out = (float*)d_out;
    float* a1  = out;                      // [N, N]
    float* b   = out + (size_t)N * N;      // [N, 3]

    fused_gqa_kernel<<<GRID, T>>>(
        x, wq1, bq1, wq2, bq2, wq3, bq3, wq4, bq4,
        wk1, bk1, wk2, bk2, wv1, bv1, wv2, bv2,
        wb, bb, a1, b);
}